// round 11
// baseline (speedup 1.0000x reference)
#include <cuda_runtime.h>
#include <cuda_fp16.h>

#define Bsz 128
#define Nn  1024
#define Mm  1024
#define TROWS  128             // rows per tile; 8 warps x 8 row-pairs
#define NTILES 8               // 1024 / 128
#define INV_EPS 20.0f          // 1/0.05
#define STAB 1e-8f
#define NUM_ITERS 10
#define PSTRIDE ((size_t)Bsz * Mm)

// Scratch (allocation-free rule: __device__ globals)
__device__ __half d_K[(size_t)Bsz * Nn * Mm];            // 256 MB fp16 kernel matrix
__device__ float  d_u[Bsz * Nn];
__device__ float  d_v[Bsz * Mm];
__device__ float  d_part[(size_t)NTILES * Bsz * Mm];     // 4 MB per-tile column partials

// ---------------------------------------------------------------------------
// Pass 1: K = exp(-C/eps) in fp16 (two launches so ncu -s 5 profiles k_fused)
// ---------------------------------------------------------------------------
__global__ __launch_bounds__(256) void k_exp(const float* __restrict__ C, size_t off4, size_t cnt4) {
    size_t stride = (size_t)gridDim.x * blockDim.x;
    for (size_t i = (size_t)blockIdx.x * blockDim.x + threadIdx.x; i < cnt4; i += stride) {
        size_t idx = off4 + i;
        float4 c = reinterpret_cast<const float4*>(C)[idx];
        __half2 lo = __floats2half2_rn(__expf(-c.x * INV_EPS), __expf(-c.y * INV_EPS));
        __half2 hi = __floats2half2_rn(__expf(-c.z * INV_EPS), __expf(-c.w * INV_EPS));
        union { __half2 h[2]; uint2 u; } p;
        p.h[0] = lo; p.h[1] = hi;
        reinterpret_cast<uint2*>(d_K)[idx] = p.u;
    }
}

// init partials so first fused iteration sees v = 1/(8*128) = 1/1024
__global__ __launch_bounds__(256) void k_initpart() {
    size_t i = (size_t)blockIdx.x * 256 + threadIdx.x;
    reinterpret_cast<float4*>(d_part)[i] = make_float4(128.f, 128.f, 128.f, 128.f);
}

// ---------------------------------------------------------------------------
// Fused iteration (also folds in the v-finalize of the PREVIOUS iteration):
// prologue: v[c] = 1/(sum_t part[t][b][c] + eps)  -> smem sv
// main: warp processes 8 row-pairs. Per pair: 8 independent LDG.128,
//       two tree-dots (convert inline), interleaved 5-level butterflies,
//       u0,u1 = rcp, colacc[32] += k0*u0 + k1*u1 (re-convert from raw regs).
// epilogue: 8-warp smem reduction -> d_part[tile].
// ---------------------------------------------------------------------------
__global__ __launch_bounds__(256, 2) void k_fused() {
    __shared__ float sv[Mm];                 // 4 KB
    __shared__ float spart[8 * Mm];          // 32 KB

    int t = blockIdx.x;                      // tile 0..7
    int b = blockIdx.y;                      // batch 0..127
    int warp = threadIdx.x >> 5;
    int lane = threadIdx.x & 31;

    // ---- prologue: finalize v from previous iteration's partials ----
    {
        int c4 = threadIdx.x;                // float4 index [0,256)
        const float4* P = reinterpret_cast<const float4*>(d_part + (size_t)b * Mm);
        float4 s = make_float4(0.f, 0.f, 0.f, 0.f);
#pragma unroll
        for (int tt = 0; tt < NTILES; tt++) {
            float4 p = P[(PSTRIDE / 4) * tt + c4];
            s.x += p.x; s.y += p.y; s.z += p.z; s.w += p.w;
        }
        float4 o;
        o.x = 1.0f / (s.x + STAB);
        o.y = 1.0f / (s.y + STAB);
        o.z = 1.0f / (s.z + STAB);
        o.w = 1.0f / (s.w + STAB);
        reinterpret_cast<float4*>(sv)[c4] = o;
    }
    __syncthreads();

    // lane's 32 fixed columns of v -> registers
    float vreg[32];
#pragma unroll
    for (int j = 0; j < 4; j++) {
        int base = j * 256 + lane * 8;
        float4 a0 = *reinterpret_cast<const float4*>(sv + base);
        float4 a1 = *reinterpret_cast<const float4*>(sv + base + 4);
        vreg[j*8+0] = a0.x; vreg[j*8+1] = a0.y; vreg[j*8+2] = a0.z; vreg[j*8+3] = a0.w;
        vreg[j*8+4] = a1.x; vreg[j*8+5] = a1.y; vreg[j*8+6] = a1.z; vreg[j*8+7] = a1.w;
    }

    float colacc[32];
#pragma unroll
    for (int i = 0; i < 32; i++) colacc[i] = 0.0f;

    const __half* Ktile = d_K + ((size_t)b * Nn + t * TROWS) * Mm;

#pragma unroll 2
    for (int rr = 0; rr < 8; rr++) {
        int pr = rr * 8 + warp;              // pair index; rows 2pr, 2pr+1
        const __half* Krow0 = Ktile + (size_t)(2 * pr) * Mm;
        const __half* Krow1 = Krow0 + Mm;

        uint4 kv0[4], kv1[4];
#pragma unroll
        for (int j = 0; j < 4; j++) {
            int base = j * 256 + lane * 8;
            kv0[j] = *reinterpret_cast<const uint4*>(Krow0 + base);
            kv1[j] = *reinterpret_cast<const uint4*>(Krow1 + base);
        }

        // tree dots, conversions inline
        float p0[4] = {0.f, 0.f, 0.f, 0.f};
        float p1[4] = {0.f, 0.f, 0.f, 0.f};
#pragma unroll
        for (int j = 0; j < 4; j++) {
            union { uint4 u; __half2 h[4]; } a, c;
            a.u = kv0[j]; c.u = kv1[j];
#pragma unroll
            for (int q = 0; q < 4; q++) {
                float2 f0 = __half22float2(a.h[q]);
                float2 f1 = __half22float2(c.h[q]);
                float vx = vreg[j*8 + 2*q], vy = vreg[j*8 + 2*q + 1];
                p0[j] += f0.x * vx + f0.y * vy;
                p1[j] += f1.x * vx + f1.y * vy;
            }
        }
        float acc0 = (p0[0] + p0[1]) + (p0[2] + p0[3]);
        float acc1 = (p1[0] + p1[1]) + (p1[2] + p1[3]);

#pragma unroll
        for (int o = 16; o > 0; o >>= 1) {
            acc0 += __shfl_xor_sync(0xFFFFFFFFu, acc0, o);
            acc1 += __shfl_xor_sync(0xFFFFFFFFu, acc1, o);
        }
        float u0 = 1.0f / (acc0 + STAB);
        float u1 = 1.0f / (acc1 + STAB);
        if (lane == 0) {
            int gr = b * Nn + t * TROWS + 2 * pr;
            *reinterpret_cast<float2*>(d_u + gr) = make_float2(u0, u1);
        }

        // column accumulation (re-convert from raw regs)
#pragma unroll
        for (int j = 0; j < 4; j++) {
            union { uint4 u; __half2 h[4]; } a, c;
            a.u = kv0[j]; c.u = kv1[j];
#pragma unroll
            for (int q = 0; q < 4; q++) {
                float2 f0 = __half22float2(a.h[q]);
                float2 f1 = __half22float2(c.h[q]);
                colacc[j*8 + 2*q]     += f0.x * u0 + f1.x * u1;
                colacc[j*8 + 2*q + 1] += f0.y * u0 + f1.y * u1;
            }
        }
    }

    // per-warp partials -> smem
#pragma unroll
    for (int j = 0; j < 4; j++) {
        float* dst = spart + warp * Mm + j * 256 + lane * 8;
        *reinterpret_cast<float4*>(dst)     = make_float4(colacc[j*8+0], colacc[j*8+1], colacc[j*8+2], colacc[j*8+3]);
        *reinterpret_cast<float4*>(dst + 4) = make_float4(colacc[j*8+4], colacc[j*8+5], colacc[j*8+6], colacc[j*8+7]);
    }
    __syncthreads();

    // block reduce 8 warps -> d_part[tile]
    {
        int c = threadIdx.x * 4;
        float4 s = make_float4(0.f, 0.f, 0.f, 0.f);
#pragma unroll
        for (int w = 0; w < 8; w++) {
            float4 p = *reinterpret_cast<const float4*>(spart + w * Mm + c);
            s.x += p.x; s.y += p.y; s.z += p.z; s.w += p.w;
        }
        *reinterpret_cast<float4*>(d_part + (size_t)t * PSTRIDE + b * Mm + c) = s;
    }
}

// ---------------------------------------------------------------------------
// Final v materialization (once, before k_out)
// ---------------------------------------------------------------------------
__global__ __launch_bounds__(256) void k_fin() {
    int i4 = blockIdx.x * 256 + threadIdx.x;   // [0, B*M/4)
    float4 s = make_float4(0.f, 0.f, 0.f, 0.f);
#pragma unroll
    for (int t = 0; t < NTILES; t++) {
        float4 p = reinterpret_cast<const float4*>(d_part + (size_t)t * PSTRIDE)[i4];
        s.x += p.x; s.y += p.y; s.z += p.z; s.w += p.w;
    }
    float4 o;
    o.x = 1.0f / (s.x + STAB);
    o.y = 1.0f / (s.y + STAB);
    o.z = 1.0f / (s.z + STAB);
    o.w = 1.0f / (s.w + STAB);
    reinterpret_cast<float4*>(d_v)[i4] = o;
}

// ---------------------------------------------------------------------------
// out = u[:,None] * K * v[None,:]   — K read back in fp16
// ---------------------------------------------------------------------------
__global__ __launch_bounds__(256) void k_out(float* __restrict__ out) {
    size_t n4 = (size_t)Bsz * Nn * Mm / 4;
    size_t stride = (size_t)gridDim.x * blockDim.x;
    for (size_t i = (size_t)blockIdx.x * blockDim.x + threadIdx.x; i < n4; i += stride) {
        size_t e   = i * 4;
        int    m   = (int)(e & (Mm - 1));
        size_t row = e >> 10;          // b*N + n
        int    b   = (int)(row >> 10);
        float  un  = d_u[row];
        union { uint2 u; __half2 h[2]; } p;
        p.u = reinterpret_cast<const uint2*>(d_K)[i];
        float2 k0 = __half22float2(p.h[0]);
        float2 k1 = __half22float2(p.h[1]);
        float4 vv = *reinterpret_cast<const float4*>(d_v + b * Mm + m);
        float4 o;
        o.x = un * k0.x * vv.x;
        o.y = un * k0.y * vv.y;
        o.z = un * k1.x * vv.z;
        o.w = un * k1.y * vv.w;
        reinterpret_cast<float4*>(out)[i] = o;
    }
}

extern "C" void kernel_launch(void* const* d_in, const int* in_sizes, int n_in,
                              void* d_out, int out_size) {
    const float* C   = (const float*)d_in[0];
    float*       out = (float*)d_out;

    size_t n4   = (size_t)Bsz * Nn * Mm / 4;
    size_t half = n4 / 2;
    k_exp<<<8192, 256>>>(C, 0, half);                       // 1
    k_exp<<<8192, 256>>>(C, half, half);                    // 2
    k_initpart<<<(NTILES * Bsz * Mm) / (4 * 256), 256>>>(); // 3
    dim3 grid(NTILES, Bsz);
    for (int it = 0; it < NUM_ITERS; it++)
        k_fused<<<grid, 256>>>();                           // 4..13 (6th = profiled)
    k_fin<<<(Bsz * Mm) / (4 * 256), 256>>>();
    k_out<<<8192, 256>>>(out);
}